// round 12
// baseline (speedup 1.0000x reference)
#include <cuda_runtime.h>
#include <cuda_bf16.h>
#include <math.h>
#include <stdint.h>

#define B_    8
#define N_    1000
#define E_    4
#define D_    64
#define AD_   32
#define NE_   4000      // E_ * N_
#define ACOLS 8000      // 2 * NE_

// ---------------- scratch (device globals; no allocations allowed) ----------
// s stored TRANSPOSED [ (b*2+io) ][ f(64) ][ k(4000) ] as fp32 pre-rounded to tf32
__device__ __align__(16) float g_sT  [16 * 64 * NE_];    // 16.4 MB
__device__ __align__(16) float g_a_in [B_ * N_  * D_];   // 2 MB
__device__ __align__(16) float g_a_out[B_ * N_  * D_];   // 2 MB
__device__ __align__(16) float g_st1  [B_ * N_  * D_];   // 2 MB
__device__ __align__(16) float g_st2  [B_ * N_  * D_];   // 2 MB
// pre-transposed gate weights [k(192)][f(64)]
__device__ __align__(16) float g_WrT[192 * 64];
__device__ __align__(16) float g_WzT[192 * 64];
__device__ __align__(16) float g_WhT[192 * 64];

// ---------------- helpers ---------------------------------------------------
__device__ __forceinline__ uint32_t smem_u32(const void* p) {
    uint32_t a;
    asm("{ .reg .u64 t; cvta.to.shared.u64 t, %1; cvt.u32.u64 %0, t; }"
        : "=r"(a) : "l"(p));
    return a;
}
// swizzle for 256-byte rows: rows permute the 16B-chunk index within 128B
__device__ __forceinline__ uint32_t sw256(uint32_t off) {
    return off ^ ((off >> 4) & 0x70);
}
__device__ __forceinline__ uint32_t f2tf32(float v) {
    uint32_t u;
    asm("cvt.rna.tf32.f32 %0, %1;" : "=r"(u) : "f"(v));
    return u;
}
__device__ __forceinline__ void ldsm_x4(uint32_t* d, uint32_t addr) {
    asm volatile("ldmatrix.sync.aligned.m8n8.x4.shared.b16 {%0,%1,%2,%3}, [%4];"
        : "=r"(d[0]), "=r"(d[1]), "=r"(d[2]), "=r"(d[3]) : "r"(addr));
}
__device__ __forceinline__ void ldsm_x2(uint32_t* d, uint32_t addr) {
    asm volatile("ldmatrix.sync.aligned.m8n8.x2.shared.b16 {%0,%1}, [%2];"
        : "=r"(d[0]), "=r"(d[1]) : "r"(addr));
}
// m16n8k8 tf32 MMA, fp32 accum
__device__ __forceinline__ void mma_tf32(float* c, const uint32_t* a, const uint32_t* b) {
    asm volatile("mma.sync.aligned.m16n8k8.row.col.f32.tf32.tf32.f32 "
        "{%0,%1,%2,%3}, {%4,%5,%6,%7}, {%8,%9}, {%0,%1,%2,%3};"
        : "+f"(c[0]), "+f"(c[1]), "+f"(c[2]), "+f"(c[3])
        : "r"(a[0]), "r"(a[1]), "r"(a[2]), "r"(a[3]), "r"(b[0]), "r"(b[1]));
}
__device__ __forceinline__ void cp_async16(uint32_t dst, const void* src, int sz) {
    asm volatile("cp.async.cg.shared.global [%0], [%1], 16, %2;"
        :: "r"(dst), "l"(src), "r"(sz) : "memory");
}
#define CP_COMMIT() asm volatile("cp.async.commit_group;" ::: "memory")
#define CP_WAIT0()  asm volatile("cp.async.wait_group 0;" ::: "memory")

// ============================================================================
// Kernel 0: pre-transpose gate weights (once per launch) [f][192] -> [k][64]
// ============================================================================
__global__ __launch_bounds__(256) void k_pret(
    const float* __restrict__ W_r,
    const float* __restrict__ W_z,
    const float* __restrict__ W_h)
{
    int idx = blockIdx.x * 256 + threadIdx.x;   // 0..12287
    if (idx < 64 * 192) {
        int f = idx / 192, k = idx - f * 192;
        int o = k * 64 + f;
        g_WrT[o] = W_r[idx];
        g_WzT[o] = W_z[idx];
        g_WhT[o] = W_h[idx];
    }
}

// ============================================================================
// Kernel 1: s_T[(b,io)][f][e*N+j] (fp32, tf32-rounded) = sum_d state*W
// io merged. grid: (16 row-tiles of 64, B, E) ; block 256
// ============================================================================
__global__ __launch_bounds__(256) void k_compute_s(
    const float* __restrict__ prop_state,
    const float* __restrict__ W_in,
    const float* __restrict__ W_out,
    int round)
{
    const float* state = round ? g_st1 : prop_state;
    const int e  = blockIdx.z;
    const int b  = blockIdx.y;
    const int j0 = blockIdx.x * 64;
    const float* sb = state + (size_t)b * N_ * D_;

    __shared__ float As[64 * 68];      // state tile [j][d]; reused stride 65 for staging
    __shared__ float Wt[2][64 * 64];   // W transposed [d][f], io = 0/1

    const int t = threadIdx.x;

    #pragma unroll
    for (int i = 0; i < 4; i++) {
        int idx = t + i * 256;
        int j   = idx >> 4;
        int dq  = (idx & 15) << 2;
        float4 v = make_float4(0.f, 0.f, 0.f, 0.f);
        if (j0 + j < N_) v = *(const float4*)(sb + (size_t)(j0 + j) * D_ + dq);
        *(float4*)&As[j * 68 + dq] = v;
    }
    {
        const float* W0 = W_in  + e * (D_ * D_);
        const float* W1 = W_out + e * (D_ * D_);
        #pragma unroll
        for (int i = 0; i < 4; i++) {
            int idx = t + i * 256;
            int f   = idx & 63;
            int dq  = (idx >> 6) << 2;
            float4 v0 = *(const float4*)(W0 + f * D_ + dq);
            float4 v1 = *(const float4*)(W1 + f * D_ + dq);
            Wt[0][(dq + 0) * 64 + f] = v0.x;
            Wt[0][(dq + 1) * 64 + f] = v0.y;
            Wt[0][(dq + 2) * 64 + f] = v0.z;
            Wt[0][(dq + 3) * 64 + f] = v0.w;
            Wt[1][(dq + 0) * 64 + f] = v1.x;
            Wt[1][(dq + 1) * 64 + f] = v1.y;
            Wt[1][(dq + 2) * 64 + f] = v1.z;
            Wt[1][(dq + 3) * 64 + f] = v1.w;
        }
    }
    __syncthreads();

    const int tx = t & 15, ty = t >> 4;
    const int r0 = ty * 4, c0 = tx * 4;
    float acc[2][4][4];
    #pragma unroll
    for (int io = 0; io < 2; io++)
        #pragma unroll
        for (int i = 0; i < 4; i++)
            #pragma unroll
            for (int j = 0; j < 4; j++) acc[io][i][j] = 0.f;

    #pragma unroll 8
    for (int d = 0; d < 64; d++) {
        float a0 = As[(r0 + 0) * 68 + d];
        float a1 = As[(r0 + 1) * 68 + d];
        float a2 = As[(r0 + 2) * 68 + d];
        float a3 = As[(r0 + 3) * 68 + d];
        float4 w0 = *(const float4*)&Wt[0][d * 64 + c0];
        float4 w1 = *(const float4*)&Wt[1][d * 64 + c0];
        acc[0][0][0] += a0 * w0.x; acc[0][0][1] += a0 * w0.y; acc[0][0][2] += a0 * w0.z; acc[0][0][3] += a0 * w0.w;
        acc[0][1][0] += a1 * w0.x; acc[0][1][1] += a1 * w0.y; acc[0][1][2] += a1 * w0.z; acc[0][1][3] += a1 * w0.w;
        acc[0][2][0] += a2 * w0.x; acc[0][2][1] += a2 * w0.y; acc[0][2][2] += a2 * w0.z; acc[0][2][3] += a2 * w0.w;
        acc[0][3][0] += a3 * w0.x; acc[0][3][1] += a3 * w0.y; acc[0][3][2] += a3 * w0.z; acc[0][3][3] += a3 * w0.w;
        acc[1][0][0] += a0 * w1.x; acc[1][0][1] += a0 * w1.y; acc[1][0][2] += a0 * w1.z; acc[1][0][3] += a0 * w1.w;
        acc[1][1][0] += a1 * w1.x; acc[1][1][1] += a1 * w1.y; acc[1][1][2] += a1 * w1.z; acc[1][1][3] += a1 * w1.w;
        acc[1][2][0] += a2 * w1.x; acc[1][2][1] += a2 * w1.y; acc[1][2][2] += a2 * w1.z; acc[1][2][3] += a2 * w1.w;
        acc[1][3][0] += a3 * w1.x; acc[1][3][1] += a3 * w1.y; acc[1][3][2] += a3 * w1.z; acc[1][3][3] += a3 * w1.w;
    }

    const int wid = t >> 5, lane = t & 31;
    #pragma unroll
    for (int io = 0; io < 2; io++) {
        __syncthreads();
        #pragma unroll
        for (int i = 0; i < 4; i++)
            #pragma unroll
            for (int j = 0; j < 4; j++)
                As[(r0 + i) * 65 + (c0 + j)] = acc[io][i][j];
        __syncthreads();

        float* bs = g_sT + (size_t)(b * 2 + io) * 64 * NE_ + (size_t)e * N_ + j0;
        #pragma unroll
        for (int pass = 0; pass < 8; pass++) {
            int f  = pass * 8 + wid;
            int j2 = lane * 2;
            if (j0 + j2 < N_) {
                uint2 p;
                p.x = f2tf32(As[j2 * 65 + f]);
                p.y = f2tf32(As[(j2 + 1) * 65 + f]);
                *reinterpret_cast<uint2*>(bs + (size_t)f * NE_ + j2) = p;
            }
        }
    }
}

// ============================================================================
// Kernel 2 (mma.sync TF32 single-pass, double-buffered):
//   a[b,io,i,f] = sum_k A[b,i,io*4000+k] * s[b,io,k,f]
// CTA tile 128x64, K chunks of 64 (8 x k8 steps). 8 warps 4(m)x2(n).
// A: 128x64 fp32 (32KB, 256B rows, sw256); B: 64x64 fp32 (16KB).
// grid: (8, B, 2) ; block 256 ; smem 96KB (2 stages x 48KB)
// ============================================================================
#define MM_A 0
#define MM_B 32768
#define MM_STAGE 49152
#define MM_SMEM  (2 * MM_STAGE)
#define MM_NCHUNK 63

__device__ __forceinline__ void mm_prefetchA(
    const float* __restrict__ Ab, int i0, int kc, int t, float4* ra)
{
    const int arow = t >> 4, acol = (t & 15) * 4;
    #pragma unroll
    for (int rep = 0; rep < 8; rep++) {
        int r = i0 + arow + rep * 16;
        int k = kc + acol;
        ra[rep] = (r < N_ && k < NE_)
                ? *(const float4*)(Ab + (size_t)r * ACOLS + k)
                : make_float4(0.f, 0.f, 0.f, 0.f);
    }
}
__device__ __forceinline__ void mm_cp_s(
    uint32_t stg_base, const float* __restrict__ Sg, int kc, int t)
{
    #pragma unroll
    for (int rep = 0; rep < 4; rep++) {
        int idx = t + rep * 256;            // 0..1023
        int f = idx >> 4;                   // 0..63
        int u = idx & 15;                   // 16B unit within 256B row
        int k = kc + u * 4;
        int sz = (k < NE_) ? 16 : 0;
        int ksafe = (k < NE_) ? k : (NE_ - 4);
        uint32_t sw = sw256((uint32_t)(f * 256 + u * 16));
        cp_async16(stg_base + MM_B + sw, Sg + (size_t)f * NE_ + ksafe, sz);
    }
}
__device__ __forceinline__ void mm_storeA(char* stg, int t, const float4* ra)
{
    char* Am = stg + MM_A;
    const int arow = t >> 4, acolb = (t & 15) * 16;
    #pragma unroll
    for (int rep = 0; rep < 8; rep++) {
        int r = arow + rep * 16;
        uint32_t sw = sw256((uint32_t)(r * 256 + acolb));
        uint4 q;
        q.x = f2tf32(ra[rep].x);
        q.y = f2tf32(ra[rep].y);
        q.z = f2tf32(ra[rep].z);
        q.w = f2tf32(ra[rep].w);
        *(uint4*)(Am + sw) = q;
    }
}

__global__ __launch_bounds__(256, 1) void k_prop_mma(const float* __restrict__ A)
{
    extern __shared__ char smem[];
    const int io = blockIdx.z, b = blockIdx.y;
    const int i0 = blockIdx.x * 128;
    const int t = threadIdx.x, wid = t >> 5, lane = t & 31;
    const float* Ab = A + (size_t)b * N_ * ACOLS + (size_t)io * NE_;
    const float* Sg = g_sT + (size_t)(b * 2 + io) * 64 * NE_;
    float* O = (io ? g_a_out : g_a_in) + (size_t)b * N_ * D_;

    const uint32_t sb = smem_u32(smem);
    const int wm = wid & 3, wn = wid >> 2;

    // ldmatrix source rows/cols (f32 elements, 256B rows)
    const int a_r  = wm * 32 + (lane & 15);         // A row
    const int a_kb = (lane >> 4) * 16;              // +4 f32 cols for upper half
    const int b_f  = lane & 7;                      // B row within n-octet
    const int b_kb = ((lane >> 3) & 1) * 16;        // +4 f32 cols

    float acc[2][4][4];
    #pragma unroll
    for (int mt = 0; mt < 2; mt++)
        #pragma unroll
        for (int nt = 0; nt < 4; nt++)
            #pragma unroll
            for (int r = 0; r < 4; r++) acc[mt][nt][r] = 0.f;

    float4 ra[8];

    // prologue: fill stage 0
    mm_prefetchA(Ab, i0, 0, t, ra);
    mm_cp_s(sb, Sg, 0, t);
    CP_COMMIT();
    mm_storeA(smem, t, ra);
    CP_WAIT0();
    __syncthreads();

    for (int c = 0; c < MM_NCHUNK; c++) {
        const int p = c & 1;
        const uint32_t stage = sb + (uint32_t)p * MM_STAGE;
        char* nstg = smem + (p ^ 1) * MM_STAGE;

        const bool more = (c + 1 < MM_NCHUNK);
        if (more) {
            mm_prefetchA(Ab, i0, (c + 1) * 64, t, ra);
            mm_cp_s(sb + (uint32_t)(p ^ 1) * MM_STAGE, Sg, (c + 1) * 64, t);
            CP_COMMIT();
        }

        #pragma unroll
        for (int ks = 0; ks < 8; ks++) {          // 8 steps of k8
            uint32_t a[2][4];
            #pragma unroll
            for (int mt = 0; mt < 2; mt++) {
                uint32_t off = sw256((uint32_t)((a_r + mt * 16) * 256 + ks * 32 + a_kb));
                ldsm_x4(a[mt], stage + MM_A + off);
            }
            uint32_t bfr[4][2];
            #pragma unroll
            for (int nt = 0; nt < 4; nt++) {
                int f = wn * 32 + nt * 8 + b_f;
                uint32_t off = sw256((uint32_t)(f * 256 + ks * 32 + b_kb));
                ldsm_x2(bfr[nt], stage + MM_B + off);
            }
            #pragma unroll
            for (int mt = 0; mt < 2; mt++)
                #pragma unroll
                for (int nt = 0; nt < 4; nt++)
                    mma_tf32(acc[mt][nt], a[mt], bfr[nt]);
        }

        if (more) mm_storeA(nstg, t, ra);         // overlaps MMA drain
        CP_WAIT0();
        __syncthreads();
    }

    const int orow = wm * 32 + (lane >> 2);
    const int ocol = wn * 32 + 2 * (lane & 3);
    #pragma unroll
    for (int mt = 0; mt < 2; mt++) {
        #pragma unroll
        for (int nt = 0; nt < 4; nt++) {
            int r1 = i0 + orow + mt * 16;
            int r2 = r1 + 8;
            int cc = ocol + nt * 8;
            if (r1 < N_)
                *(float2*)(O + (size_t)r1 * D_ + cc) = make_float2(acc[mt][nt][0], acc[mt][nt][1]);
            if (r2 < N_)
                *(float2*)(O + (size_t)r2 * D_ + cc) = make_float2(acc[mt][nt][2], acc[mt][nt][3]);
        }
    }
}

// ============================================================================
// Kernel 3: gates + state update (unchanged from R11)
// ============================================================================
__global__ __launch_bounds__(256) void k_gates(
    const float* __restrict__ prop_state,
    int round)
{
    const float* state = round ? g_st1 : prop_state;
    float* out_state   = round ? g_st2 : g_st1;
    const int b  = blockIdx.y;
    const int j0 = blockIdx.x * 64;

    extern __shared__ float smg[];
    float* a_sm = smg;
    float* Wr   = smg + 64 * 196;
    float* Wz   = Wr + 192 * 64;
    float* Wh   = Wz + 192 * 64;

    const int t = threadIdx.x;
    const float* ai = g_a_in  + (size_t)b * N_ * D_;
    const float* ao = g_a_out + (size_t)b * N_ * D_;
    const float* st = state   + (size_t)b * N_ * D_;

    #pragma unroll
    for (int i = 0; i < 4; i++) {
        int idx = t + i * 256;
        int j = idx >> 4, fq = (idx & 15) << 2;
        int row = j0 + j;
        float4 z4 = make_float4(0.f, 0.f, 0.f, 0.f);
        size_t g = (size_t)row * D_ + fq;
        bool v = (row < N_);
        *(float4*)&a_sm[j * 196 +       fq] = v ? *(const float4*)(ai + g) : z4;
        *(float4*)&a_sm[j * 196 +  64 + fq] = v ? *(const float4*)(ao + g) : z4;
        *(float4*)&a_sm[j * 196 + 128 + fq] = v ? *(const float4*)(st + g) : z4;
    }
    #pragma unroll
    for (int i = 0; i < 12; i++) {
        int idx4 = (t + i * 256) * 4;
        *(float4*)&Wr[idx4] = *(const float4*)(g_WrT + idx4);
        *(float4*)&Wz[idx4] = *(const float4*)(g_WzT + idx4);
        *(float4*)&Wh[idx4] = *(const float4*)(g_WhT + idx4);
    }
    __syncthreads();

    const int tx = t & 15, ty = t >> 4;
    const int r0 = ty * 4, c0 = tx * 4;

    float aR[4][4], aZ[4][4];
    #pragma unroll
    for (int i = 0; i < 4; i++)
        #pragma unroll
        for (int j = 0; j < 4; j++) { aR[i][j] = 0.f; aZ[i][j] = 0.f; }

    #pragma unroll 8
    for (int k = 0; k < 192; k++) {
        float a0 = a_sm[(r0 + 0) * 196 + k];
        float a1 = a_sm[(r0 + 1) * 196 + k];
        float a2 = a_sm[(r0 + 2) * 196 + k];
        float a3 = a_sm[(r0 + 3) * 196 + k];
        float4 wr = *(const float4*)&Wr[k * 64 + c0];
        float4 wz = *(const float4*)&Wz[k * 64 + c0];
        aR[0][0] += a0 * wr.x; aR[0][1] += a0 * wr.y; aR[0][2] += a0 * wr.z; aR[0][3] += a0 * wr.w;
        aR[1][0] += a1 * wr.x; aR[1][1] += a1 * wr.y; aR[1][2] += a1 * wr.z; aR[1][3] += a1 * wr.w;
        aR[2][0] += a2 * wr.x; aR[2][1] += a2 * wr.y; aR[2][2] += a2 * wr.z; aR[2][3] += a2 * wr.w;
        aR[3][0] += a3 * wr.x; aR[3][1] += a3 * wr.y; aR[3][2] += a3 * wr.z; aR[3][3] += a3 * wr.w;
        aZ[0][0] += a0 * wz.x; aZ[0][1] += a0 * wz.y; aZ[0][2] += a0 * wz.z; aZ[0][3] += a0 * wz.w;
        aZ[1][0] += a1 * wz.x; aZ[1][1] += a1 * wz.y; aZ[1][2] += a1 * wz.z; aZ[1][3] += a1 * wz.w;
        aZ[2][0] += a2 * wz.x; aZ[2][1] += a2 * wz.y; aZ[2][2] += a2 * wz.z; aZ[2][3] += a2 * wz.w;
        aZ[3][0] += a3 * wz.x; aZ[3][1] += a3 * wz.y; aZ[3][2] += a3 * wz.z; aZ[3][3] += a3 * wz.w;
    }

    float rg[4][4], zg[4][4], sOrig[4][4];
    #pragma unroll
    for (int i = 0; i < 4; i++)
        #pragma unroll
        for (int j = 0; j < 4; j++) {
            rg[i][j] = 1.f / (1.f + expf(-aR[i][j]));
            zg[i][j] = 1.f / (1.f + expf(-aZ[i][j]));
            sOrig[i][j] = a_sm[(r0 + i) * 196 + 128 + c0 + j];
        }
    __syncthreads();
    #pragma unroll
    for (int i = 0; i < 4; i++)
        #pragma unroll
        for (int j = 0; j < 4; j++)
            a_sm[(r0 + i) * 196 + 128 + c0 + j] = rg[i][j] * sOrig[i][j];
    __syncthreads();

    float aH[4][4];
    #pragma unroll
    for (int i = 0; i < 4; i++)
        #pragma unroll
        for (int j = 0; j < 4; j++) aH[i][j] = 0.f;

    #pragma unroll 8
    for (int k = 0; k < 192; k++) {
        float a0 = a_sm[(r0 + 0) * 196 + k];
        float a1 = a_sm[(r0 + 1) * 196 + k];
        float a2 = a_sm[(r0 + 2) * 196 + k];
        float a3 = a_sm[(r0 + 3) * 196 + k];
        float4 wh = *(const float4*)&Wh[k * 64 + c0];
        aH[0][0] += a0 * wh.x; aH[0][1] += a0 * wh.y; aH[0][2] += a0 * wh.z; aH[0][3] += a0 * wh.w;
        aH[1][0] += a1 * wh.x; aH[1][1] += a1 * wh.y; aH[1][2] += a1 * wh.z; aH[1][3] += a1 * wh.w;
        aH[2][0] += a2 * wh.x; aH[2][1] += a2 * wh.y; aH[2][2] += a2 * wh.z; aH[2][3] += a2 * wh.w;
        aH[3][0] += a3 * wh.x; aH[3][1] += a3 * wh.y; aH[3][2] += a3 * wh.z; aH[3][3] += a3 * wh.w;
    }

    float* od = out_state + (size_t)b * N_ * D_;
    #pragma unroll
    for (int i = 0; i < 4; i++) {
        int row = j0 + r0 + i;
        if (row < N_) {
            float o[4];
            #pragma unroll
            for (int j = 0; j < 4; j++) {
                float h = tanhf(aH[i][j]);
                o[j] = (1.f - zg[i][j]) * sOrig[i][j] + zg[i][j] * h;
            }
            *(float4*)(od + (size_t)row * D_ + c0) = make_float4(o[0], o[1], o[2], o[3]);
        }
    }
}

// ============================================================================
// Kernel 4: readout (unchanged)
// ============================================================================
__global__ __launch_bounds__(256) void k_readout(
    const float* __restrict__ annot,
    const float* __restrict__ Wo1,
    const float* __restrict__ Wo2,
    float* __restrict__ out)
{
    __shared__ float W1[64 * 97];
    __shared__ float W2s[64];
    __shared__ float rowbuf[4][96];
    __shared__ float partial[4][2];

    const int t = threadIdx.x;
    for (int i = t; i < 64 * 96; i += 256) {
        int f = i / 96, k = i - f * 96;
        W1[f * 97 + k] = Wo1[i];
    }
    if (t < 64) W2s[t] = Wo2[t];

    const int slot = t >> 6;
    const int lane = t & 63;
    const int row  = blockIdx.x * 4 + slot;
    const int b    = row / N_;
    const int i    = row - b * N_;

    for (int k = lane; k < 96; k += 64) {
        float v = (k < 64) ? g_st2[((size_t)b * N_ + i) * D_ + k]
                           : annot[((size_t)b * N_ + i) * AD_ + (k - 64)];
        rowbuf[slot][k] = v;
    }
    __syncthreads();

    float acc = 0.f;
    #pragma unroll 8
    for (int k = 0; k < 96; k++)
        acc += rowbuf[slot][k] * W1[lane * 97 + k];
    float v = tanhf(acc) * W2s[lane];

    #pragma unroll
    for (int off = 16; off > 0; off >>= 1)
        v += __shfl_down_sync(0xffffffffu, v, off);
    if ((t & 31) == 0) partial[slot][(t >> 5) & 1] = v;
    __syncthreads();
    if (lane == 0) out[row] = partial[slot][0] + partial[slot][1];
}

// ============================================================================
extern "C" void kernel_launch(void* const* d_in, const int* in_sizes, int n_in,
                              void* d_out, int out_size)
{
    const float* prop_state = (const float*)d_in[0];
    const float* annotation = (const float*)d_in[1];
    const float* A          = (const float*)d_in[2];
    const float* W_in       = (const float*)d_in[3];
    const float* W_out      = (const float*)d_in[4];
    const float* W_r        = (const float*)d_in[5];
    const float* W_z        = (const float*)d_in[6];
    const float* W_h        = (const float*)d_in[7];
    const float* Wo1        = (const float*)d_in[8];
    const float* Wo2        = (const float*)d_in[9];
    float* out = (float*)d_out;

    const int GATES_SMEM = (64 * 196 + 3 * 192 * 64) * (int)sizeof(float);
    cudaFuncSetAttribute(k_gates, cudaFuncAttributeMaxDynamicSharedMemorySize, GATES_SMEM);
    cudaFuncSetAttribute(k_prop_mma, cudaFuncAttributeMaxDynamicSharedMemorySize, MM_SMEM);

    k_pret<<<48, 256>>>(W_r, W_z, W_h);
    for (int round = 0; round < 2; round++) {
        k_compute_s<<<dim3(16, B_, 4), 256>>>(prop_state, W_in, W_out, round);
        k_prop_mma<<<dim3(8, B_, 2), 256, MM_SMEM>>>(A);
        k_gates<<<dim3(16, B_), 256, GATES_SMEM>>>(prop_state, round);
    }
    k_readout<<<2000, 256>>>(annotation, Wo1, Wo2, out);
}

// round 13
// speedup vs baseline: 1.5965x; 1.5965x over previous
#include <cuda_runtime.h>
#include <cuda_fp16.h>
#include <math.h>
#include <stdint.h>

#define B_    8
#define N_    1000
#define E_    4
#define D_    64
#define AD_   32
#define NE_   4000      // E_ * N_
#define ACOLS 8000      // 2 * NE_

// ---------------- scratch (device globals; no allocations allowed) ----------
// s stored TRANSPOSED [ (b*2+io) ][ f(64) ][ k(4000) ] as fp16
__device__ __align__(16) __half g_sT[16 * 64 * NE_];     // 8.2 MB
__device__ __align__(16) float g_a_in [B_ * N_  * D_];   // 2 MB
__device__ __align__(16) float g_a_out[B_ * N_  * D_];   // 2 MB
__device__ __align__(16) float g_st1  [B_ * N_  * D_];   // 2 MB
__device__ __align__(16) float g_st2  [B_ * N_  * D_];   // 2 MB
// pre-transposed gate weights [k(192)][f(64)]
__device__ __align__(16) float g_WrT[192 * 64];
__device__ __align__(16) float g_WzT[192 * 64];
__device__ __align__(16) float g_WhT[192 * 64];

// ---------------- helpers ---------------------------------------------------
__device__ __forceinline__ uint32_t smem_u32(const void* p) {
    uint32_t a;
    asm("{ .reg .u64 t; cvta.to.shared.u64 t, %1; cvt.u32.u64 %0, t; }"
        : "=r"(a) : "l"(p));
    return a;
}
__device__ __forceinline__ uint32_t sw128(uint32_t off) {
    return off ^ ((off >> 3) & 0x70);
}
// pack two fp32 -> fp16x2 (v0 in low half = lower k index)
__device__ __forceinline__ uint32_t pack_f16x2(float v0, float v1) {
    uint32_t r;
    asm("cvt.rn.f16x2.f32 %0, %1, %2;" : "=r"(r) : "f"(v1), "f"(v0));
    return r;
}
__device__ __forceinline__ void ldsm_x4(uint32_t* d, uint32_t addr) {
    asm volatile("ldmatrix.sync.aligned.m8n8.x4.shared.b16 {%0,%1,%2,%3}, [%4];"
        : "=r"(d[0]), "=r"(d[1]), "=r"(d[2]), "=r"(d[3]) : "r"(addr));
}
__device__ __forceinline__ void ldsm_x2(uint32_t* d, uint32_t addr) {
    asm volatile("ldmatrix.sync.aligned.m8n8.x2.shared.b16 {%0,%1}, [%2];"
        : "=r"(d[0]), "=r"(d[1]) : "r"(addr));
}
__device__ __forceinline__ void mma_f16(float* c, const uint32_t* a, const uint32_t* b) {
    asm volatile("mma.sync.aligned.m16n8k16.row.col.f32.f16.f16.f32 "
        "{%0,%1,%2,%3}, {%4,%5,%6,%7}, {%8,%9}, {%0,%1,%2,%3};"
        : "+f"(c[0]), "+f"(c[1]), "+f"(c[2]), "+f"(c[3])
        : "r"(a[0]), "r"(a[1]), "r"(a[2]), "r"(a[3]), "r"(b[0]), "r"(b[1]));
}
__device__ __forceinline__ void cp_async16(uint32_t dst, const void* src, int sz) {
    asm volatile("cp.async.cg.shared.global [%0], [%1], 16, %2;"
        :: "r"(dst), "l"(src), "r"(sz) : "memory");
}
#define CP_COMMIT() asm volatile("cp.async.commit_group;" ::: "memory")
#define CP_WAIT0()  asm volatile("cp.async.wait_group 0;" ::: "memory")

// ============================================================================
// Kernel 0: pre-transpose gate weights (once per launch) [f][192] -> [k][64]
// ============================================================================
__global__ __launch_bounds__(256) void k_pret(
    const float* __restrict__ W_r,
    const float* __restrict__ W_z,
    const float* __restrict__ W_h)
{
    int idx = blockIdx.x * 256 + threadIdx.x;   // 0..12287
    if (idx < 64 * 192) {
        int f = idx / 192, k = idx - f * 192;
        int o = k * 64 + f;
        g_WrT[o] = W_r[idx];
        g_WzT[o] = W_z[idx];
        g_WhT[o] = W_h[idx];
    }
}

// ============================================================================
// Kernel 1: s_T[(b,io)][f][e*N+j] (fp16) = sum_d state[b,j,d]*W[e,f,d]
// io merged. grid: (16 row-tiles of 64, B, E) ; block 256
// ============================================================================
__global__ __launch_bounds__(256) void k_compute_s(
    const float* __restrict__ prop_state,
    const float* __restrict__ W_in,
    const float* __restrict__ W_out,
    int round)
{
    const float* state = round ? g_st1 : prop_state;
    const int e  = blockIdx.z;
    const int b  = blockIdx.y;
    const int j0 = blockIdx.x * 64;
    const float* sb = state + (size_t)b * N_ * D_;

    __shared__ float As[64 * 68];      // state tile [j][d]; reused stride 65 for staging
    __shared__ float Wt[2][64 * 64];   // W transposed [d][f], io = 0/1

    const int t = threadIdx.x;

    #pragma unroll
    for (int i = 0; i < 4; i++) {
        int idx = t + i * 256;
        int j   = idx >> 4;
        int dq  = (idx & 15) << 2;
        float4 v = make_float4(0.f, 0.f, 0.f, 0.f);
        if (j0 + j < N_) v = *(const float4*)(sb + (size_t)(j0 + j) * D_ + dq);
        *(float4*)&As[j * 68 + dq] = v;
    }
    {
        const float* W0 = W_in  + e * (D_ * D_);
        const float* W1 = W_out + e * (D_ * D_);
        #pragma unroll
        for (int i = 0; i < 4; i++) {
            int idx = t + i * 256;
            int f   = idx & 63;
            int dq  = (idx >> 6) << 2;
            float4 v0 = *(const float4*)(W0 + f * D_ + dq);
            float4 v1 = *(const float4*)(W1 + f * D_ + dq);
            Wt[0][(dq + 0) * 64 + f] = v0.x;
            Wt[0][(dq + 1) * 64 + f] = v0.y;
            Wt[0][(dq + 2) * 64 + f] = v0.z;
            Wt[0][(dq + 3) * 64 + f] = v0.w;
            Wt[1][(dq + 0) * 64 + f] = v1.x;
            Wt[1][(dq + 1) * 64 + f] = v1.y;
            Wt[1][(dq + 2) * 64 + f] = v1.z;
            Wt[1][(dq + 3) * 64 + f] = v1.w;
        }
    }
    __syncthreads();

    const int tx = t & 15, ty = t >> 4;
    const int r0 = ty * 4, c0 = tx * 4;
    float acc[2][4][4];
    #pragma unroll
    for (int io = 0; io < 2; io++)
        #pragma unroll
        for (int i = 0; i < 4; i++)
            #pragma unroll
            for (int j = 0; j < 4; j++) acc[io][i][j] = 0.f;

    #pragma unroll 8
    for (int d = 0; d < 64; d++) {
        float a0 = As[(r0 + 0) * 68 + d];
        float a1 = As[(r0 + 1) * 68 + d];
        float a2 = As[(r0 + 2) * 68 + d];
        float a3 = As[(r0 + 3) * 68 + d];
        float4 w0 = *(const float4*)&Wt[0][d * 64 + c0];
        float4 w1 = *(const float4*)&Wt[1][d * 64 + c0];
        acc[0][0][0] += a0 * w0.x; acc[0][0][1] += a0 * w0.y; acc[0][0][2] += a0 * w0.z; acc[0][0][3] += a0 * w0.w;
        acc[0][1][0] += a1 * w0.x; acc[0][1][1] += a1 * w0.y; acc[0][1][2] += a1 * w0.z; acc[0][1][3] += a1 * w0.w;
        acc[0][2][0] += a2 * w0.x; acc[0][2][1] += a2 * w0.y; acc[0][2][2] += a2 * w0.z; acc[0][2][3] += a2 * w0.w;
        acc[0][3][0] += a3 * w0.x; acc[0][3][1] += a3 * w0.y; acc[0][3][2] += a3 * w0.z; acc[0][3][3] += a3 * w0.w;
        acc[1][0][0] += a0 * w1.x; acc[1][0][1] += a0 * w1.y; acc[1][0][2] += a0 * w1.z; acc[1][0][3] += a0 * w1.w;
        acc[1][1][0] += a1 * w1.x; acc[1][1][1] += a1 * w1.y; acc[1][1][2] += a1 * w1.z; acc[1][1][3] += a1 * w1.w;
        acc[1][2][0] += a2 * w1.x; acc[1][2][1] += a2 * w1.y; acc[1][2][2] += a2 * w1.z; acc[1][2][3] += a2 * w1.w;
        acc[1][3][0] += a3 * w1.x; acc[1][3][1] += a3 * w1.y; acc[1][3][2] += a3 * w1.z; acc[1][3][3] += a3 * w1.w;
    }

    const int wid = t >> 5, lane = t & 31;
    #pragma unroll
    for (int io = 0; io < 2; io++) {
        __syncthreads();
        #pragma unroll
        for (int i = 0; i < 4; i++)
            #pragma unroll
            for (int j = 0; j < 4; j++)
                As[(r0 + i) * 65 + (c0 + j)] = acc[io][i][j];
        __syncthreads();

        __half* bs = g_sT + (size_t)(b * 2 + io) * 64 * NE_ + (size_t)e * N_ + j0;
        #pragma unroll
        for (int pass = 0; pass < 8; pass++) {
            int f  = pass * 8 + wid;
            int j2 = lane * 2;
            if (j0 + j2 < N_) {
                uint32_t p = pack_f16x2(As[j2 * 65 + f], As[(j2 + 1) * 65 + f]);
                *reinterpret_cast<uint32_t*>(bs + (size_t)f * NE_ + j2) = p;
            }
        }
    }
}

// ============================================================================
// Kernel 2 (mma.sync FP16 single-pass, double-buffered):
//   a[b,io,i,f] = sum_k A[b,i,io*4000+k] * s[b,io,k,f]
// CTA tile 128x64, K chunks of 64 (4 x k16 steps). 8 warps 4(m)x2(n).
// A: 128x64 fp16 (16KB, 128B rows, sw128); B: 64x64 fp16 (8KB).
// grid: (8, B, 2) ; block 256 ; smem 48KB (2 stages x 24KB)
// ============================================================================
#define MM_A 0
#define MM_B 16384
#define MM_STAGE 24576
#define MM_SMEM  (2 * MM_STAGE)
#define MM_NCHUNK 63

__device__ __forceinline__ void mm_prefetchA(
    const float* __restrict__ Ab, int i0, int kc, int t, float4* ra)
{
    const int arow = t >> 4, acol = (t & 15) * 4;
    #pragma unroll
    for (int rep = 0; rep < 8; rep++) {
        int r = i0 + arow + rep * 16;
        int k = kc + acol;
        ra[rep] = (r < N_ && k < NE_)
                ? *(const float4*)(Ab + (size_t)r * ACOLS + k)
                : make_float4(0.f, 0.f, 0.f, 0.f);
    }
}
__device__ __forceinline__ void mm_cp_s(
    uint32_t stg_base, const __half* __restrict__ Sg, int kc, int t)
{
    const int sf = t >> 3, se = (t & 7) * 8;
    #pragma unroll
    for (int rep = 0; rep < 2; rep++) {
        int f = sf + rep * 32;
        int k = kc + se;
        int sz = (k < NE_) ? 16 : 0;
        int ksafe = (k < NE_) ? k : (NE_ - 8);      // clamp src addr even when sz=0
        uint32_t sw = sw128((uint32_t)(f * 128 + (t & 7) * 16));
        cp_async16(stg_base + MM_B + sw, Sg + (size_t)f * NE_ + ksafe, sz);
    }
}
__device__ __forceinline__ void mm_storeA(char* stg, int t, const float4* ra)
{
    char* Am = stg + MM_A;
    const int arow = t >> 4, acolb = (t & 15) * 8;
    #pragma unroll
    for (int rep = 0; rep < 8; rep++) {
        int r = arow + rep * 16;
        uint32_t sw = sw128((uint32_t)(r * 128 + acolb));
        uint2 hp;
        hp.x = pack_f16x2(ra[rep].x, ra[rep].y);
        hp.y = pack_f16x2(ra[rep].z, ra[rep].w);
        *(uint2*)(Am + sw) = hp;
    }
}

__global__ __launch_bounds__(256, 1) void k_prop_mma(const float* __restrict__ A)
{
    extern __shared__ char smem[];
    const int io = blockIdx.z, b = blockIdx.y;
    const int i0 = blockIdx.x * 128;
    const int t = threadIdx.x, wid = t >> 5, lane = t & 31;
    const float* Ab = A + (size_t)b * N_ * ACOLS + (size_t)io * NE_;
    const __half* Sg = g_sT + (size_t)(b * 2 + io) * 64 * NE_;
    float* O = (io ? g_a_out : g_a_in) + (size_t)b * N_ * D_;

    const uint32_t sb = smem_u32(smem);
    const int wm = wid & 3, wn = wid >> 2;

    const int a_r  = wm * 32 + (lane & 15);
    const int a_kb = (lane >> 4) * 16;
    const int b_rl = lane & 7;
    const int b_kb = ((lane >> 3) & 1) * 16;

    float acc[2][4][4];
    #pragma unroll
    for (int mt = 0; mt < 2; mt++)
        #pragma unroll
        for (int nt = 0; nt < 4; nt++)
            #pragma unroll
            for (int r = 0; r < 4; r++) acc[mt][nt][r] = 0.f;

    float4 ra[8];

    // prologue: fill stage 0
    mm_prefetchA(Ab, i0, 0, t, ra);
    mm_cp_s(sb, Sg, 0, t);
    CP_COMMIT();
    mm_storeA(smem, t, ra);
    CP_WAIT0();
    __syncthreads();

    for (int c = 0; c < MM_NCHUNK; c++) {
        const int p = c & 1;
        const uint32_t stage = sb + (uint32_t)p * MM_STAGE;
        char* nstg = smem + (p ^ 1) * MM_STAGE;

        const bool more = (c + 1 < MM_NCHUNK);
        if (more) {
            mm_prefetchA(Ab, i0, (c + 1) * 64, t, ra);
            mm_cp_s(sb + (uint32_t)(p ^ 1) * MM_STAGE, Sg, (c + 1) * 64, t);
            CP_COMMIT();
        }

        #pragma unroll
        for (int ks = 0; ks < 4; ks++) {          // 4 steps of k16
            uint32_t a[2][4];
            #pragma unroll
            for (int mt = 0; mt < 2; mt++) {
                uint32_t off = sw128((uint32_t)((a_r + mt * 16) * 128 + ks * 32 + a_kb));
                ldsm_x4(a[mt], stage + MM_A + off);
            }
            uint32_t bfr[4][2];
            #pragma unroll
            for (int nt = 0; nt < 4; nt++) {
                int f = wn * 32 + nt * 8 + b_rl;
                uint32_t off = sw128((uint32_t)(f * 128 + ks * 32 + b_kb));
                ldsm_x2(bfr[nt], stage + MM_B + off);
            }
            #pragma unroll
            for (int mt = 0; mt < 2; mt++)
                #pragma unroll
                for (int nt = 0; nt < 4; nt++)
                    mma_f16(acc[mt][nt], a[mt], bfr[nt]);
        }

        if (more) mm_storeA(nstg, t, ra);         // overlaps MMA drain
        CP_WAIT0();
        __syncthreads();
    }

    const int orow = wm * 32 + (lane >> 2);
    const int ocol = wn * 32 + 2 * (lane & 3);
    #pragma unroll
    for (int mt = 0; mt < 2; mt++) {
        #pragma unroll
        for (int nt = 0; nt < 4; nt++) {
            int r1 = i0 + orow + mt * 16;
            int r2 = r1 + 8;
            int cc = ocol + nt * 8;
            if (r1 < N_)
                *(float2*)(O + (size_t)r1 * D_ + cc) = make_float2(acc[mt][nt][0], acc[mt][nt][1]);
            if (r2 < N_)
                *(float2*)(O + (size_t)r2 * D_ + cc) = make_float2(acc[mt][nt][2], acc[mt][nt][3]);
        }
    }
}

// ============================================================================
// Kernel 3: gates + state update (unchanged from R11)
// ============================================================================
__global__ __launch_bounds__(256) void k_gates(
    const float* __restrict__ prop_state,
    int round)
{
    const float* state = round ? g_st1 : prop_state;
    float* out_state   = round ? g_st2 : g_st1;
    const int b  = blockIdx.y;
    const int j0 = blockIdx.x * 64;

    extern __shared__ float smg[];
    float* a_sm = smg;
    float* Wr   = smg + 64 * 196;
    float* Wz   = Wr + 192 * 64;
    float* Wh   = Wz + 192 * 64;

    const int t = threadIdx.x;
    const float* ai = g_a_in  + (size_t)b * N_ * D_;
    const float* ao = g_a_out + (size_t)b * N_ * D_;
    const float* st = state   + (size_t)b * N_ * D_;

    #pragma unroll
    for (int i = 0; i < 4; i++) {
        int idx = t + i * 256;
        int j = idx >> 4, fq = (idx & 15) << 2;
        int row = j0 + j;
        float4 z4 = make_float4(0.f, 0.f, 0.f, 0.f);
        size_t g = (size_t)row * D_ + fq;
        bool v = (row < N_);
        *(float4*)&a_sm[j * 196 +       fq] = v ? *(const float4*)(ai + g) : z4;
        *(float4*)&a_sm[j * 196 +  64 + fq] = v ? *(const float4*)(ao + g) : z4;
        *(float4*)&a_sm[j * 196 + 128 + fq] = v ? *(const float4*)(st + g) : z4;
    }
    #pragma unroll
    for (int i = 0; i < 12; i++) {
        int idx4 = (t + i * 256) * 4;
        *(float4*)&Wr[idx4] = *(const float4*)(g_WrT + idx4);
        *(float4*)&Wz[idx4] = *(const float4*)(g_WzT + idx4);
        *(float4*)&Wh[idx4] = *(const float4*)(g_WhT + idx4);
    }
    __syncthreads();

    const int tx = t & 15, ty = t >> 4;
    const int r0 = ty * 4, c0 = tx * 4;

    float aR[4][4], aZ[4][4];
    #pragma unroll
    for (int i = 0; i < 4; i++)
        #pragma unroll
        for (int j = 0; j < 4; j++) { aR[i][j] = 0.f; aZ[i][j] = 0.f; }

    #pragma unroll 8
    for (int k = 0; k < 192; k++) {
        float a0 = a_sm[(r0 + 0) * 196 + k];
        float a1 = a_sm[(r0 + 1) * 196 + k];
        float a2 = a_sm[(r0 + 2) * 196 + k];
        float a3 = a_sm[(r0 + 3) * 196 + k];
        float4 wr = *(const float4*)&Wr[k * 64 + c0];
        float4 wz = *(const float4*)&Wz[k * 64 + c0];
        aR[0][0] += a0 * wr.x; aR[0][1] += a0 * wr.y; aR[0][2] += a0 * wr.z; aR[0][3] += a0 * wr.w;
        aR[1][0] += a1 * wr.x; aR[1][1] += a1 * wr.y; aR[1][2] += a1 * wr.z; aR[1][3] += a1 * wr.w;
        aR[2][0] += a2 * wr.x; aR[2][1] += a2 * wr.y; aR[2][2] += a2 * wr.z; aR[2][3] += a2 * wr.w;
        aR[3][0] += a3 * wr.x; aR[3][1] += a3 * wr.y; aR[3][2] += a3 * wr.z; aR[3][3] += a3 * wr.w;
        aZ[0][0] += a0 * wz.x; aZ[0][1] += a0 * wz.y; aZ[0][2] += a0 * wz.z; aZ[0][3] += a0 * wz.w;
        aZ[1][0] += a1 * wz.x; aZ[1][1] += a1 * wz.y; aZ[1][2] += a1 * wz.z; aZ[1][3] += a1 * wz.w;
        aZ[2][0] += a2 * wz.x; aZ[2][1] += a2 * wz.y; aZ[2][2] += a2 * wz.z; aZ[2][3] += a2 * wz.w;
        aZ[3][0] += a3 * wz.x; aZ[3][1] += a3 * wz.y; aZ[3][2] += a3 * wz.z; aZ[3][3] += a3 * wz.w;
    }

    float rg[4][4], zg[4][4], sOrig[4][4];
    #pragma unroll
    for (int i = 0; i < 4; i++)
        #pragma unroll
        for (int j = 0; j < 4; j++) {
            rg[i][j] = 1.f / (1.f + expf(-aR[i][j]));
            zg[i][j] = 1.f / (1.f + expf(-aZ[i][j]));
            sOrig[i][j] = a_sm[(r0 + i) * 196 + 128 + c0 + j];
        }
    __syncthreads();
    #pragma unroll
    for (int i = 0; i < 4; i++)
        #pragma unroll
        for (int j = 0; j < 4; j++)
            a_sm[(r0 + i) * 196 + 128 + c0 + j] = rg[i][j] * sOrig[i][j];
    __syncthreads();

    float aH[4][4];
    #pragma unroll
    for (int i = 0; i < 4; i++)
        #pragma unroll
        for (int j = 0; j < 4; j++) aH[i][j] = 0.f;

    #pragma unroll 8
    for (int k = 0; k < 192; k++) {
        float a0 = a_sm[(r0 + 0) * 196 + k];
        float a1 = a_sm[(r0 + 1) * 196 + k];
        float a2 = a_sm[(r0 + 2) * 196 + k];
        float a3 = a_sm[(r0 + 3) * 196 + k];
        float4 wh = *(const float4*)&Wh[k * 64 + c0];
        aH[0][0] += a0 * wh.x; aH[0][1] += a0 * wh.y; aH[0][2] += a0 * wh.z; aH[0][3] += a0 * wh.w;
        aH[1][0] += a1 * wh.x; aH[1][1] += a1 * wh.y; aH[1][2] += a1 * wh.z; aH[1][3] += a1 * wh.w;
        aH[2][0] += a2 * wh.x; aH[2][1] += a2 * wh.y; aH[2][2] += a2 * wh.z; aH[2][3] += a2 * wh.w;
        aH[3][0] += a3 * wh.x; aH[3][1] += a3 * wh.y; aH[3][2] += a3 * wh.z; aH[3][3] += a3 * wh.w;
    }

    float* od = out_state + (size_t)b * N_ * D_;
    #pragma unroll
    for (int i = 0; i < 4; i++) {
        int row = j0 + r0 + i;
        if (row < N_) {
            float o[4];
            #pragma unroll
            for (int j = 0; j < 4; j++) {
                float h = tanhf(aH[i][j]);
                o[j] = (1.f - zg[i][j]) * sOrig[i][j] + zg[i][j] * h;
            }
            *(float4*)(od + (size_t)row * D_ + c0) = make_float4(o[0], o[1], o[2], o[3]);
        }
    }
}

// ============================================================================
// Kernel 4: readout (unchanged)
// ============================================================================
__global__ __launch_bounds__(256) void k_readout(
    const float* __restrict__ annot,
    const float* __restrict__ Wo1,
    const float* __restrict__ Wo2,
    float* __restrict__ out)
{
    __shared__ float W1[64 * 97];
    __shared__ float W2s[64];
    __shared__ float rowbuf[4][96];
    __shared__ float partial[4][2];

    const int t = threadIdx.x;
    for (int i = t; i < 64 * 96; i += 256) {
        int f = i / 96, k = i - f * 96;
        W1[f * 97 + k] = Wo1[i];
    }
    if (t < 64) W2s[t] = Wo2[t];

    const int slot = t >> 6;
    const int lane = t & 63;
    const int row  = blockIdx.x * 4 + slot;
    const int b    = row / N_;
    const int i    = row - b * N_;

    for (int k = lane; k < 96; k += 64) {
        float v = (k < 64) ? g_st2[((size_t)b * N_ + i) * D_ + k]
                           : annot[((size_t)b * N_ + i) * AD_ + (k - 64)];
        rowbuf[slot][k] = v;
    }
    __syncthreads();

    float acc = 0.f;
    #pragma unroll 8
    for (int k = 0; k < 96; k++)
        acc += rowbuf[slot][k] * W1[lane * 97 + k];
    float v = tanhf(acc) * W2s[lane];

    #pragma unroll
    for (int off = 16; off > 0; off >>= 1)
        v += __shfl_down_sync(0xffffffffu, v, off);
    if ((t & 31) == 0) partial[slot][(t >> 5) & 1] = v;
    __syncthreads();
    if (lane == 0) out[row] = partial[slot][0] + partial[slot][1];
}

// ============================================================================
extern "C" void kernel_launch(void* const* d_in, const int* in_sizes, int n_in,
                              void* d_out, int out_size)
{
    const float* prop_state = (const float*)d_in[0];
    const float* annotation = (const float*)d_in[1];
    const float* A          = (const float*)d_in[2];
    const float* W_in       = (const float*)d_in[3];
    const float* W_out      = (const float*)d_in[4];
    const float* W_r        = (const float*)d_in[5];
    const float* W_z        = (const float*)d_in[6];
    const float* W_h        = (const float*)d_in[7];
    const float* Wo1        = (const float*)d_in[8];
    const float* Wo2        = (const float*)d_in[9];
    float* out = (float*)d_out;

    const int GATES_SMEM = (64 * 196 + 3 * 192 * 64) * (int)sizeof(float);
    cudaFuncSetAttribute(k_gates, cudaFuncAttributeMaxDynamicSharedMemorySize, GATES_SMEM);
    cudaFuncSetAttribute(k_prop_mma, cudaFuncAttributeMaxDynamicSharedMemorySize, MM_SMEM);

    k_pret<<<48, 256>>>(W_r, W_z, W_h);
    for (int round = 0; round < 2; round++) {
        k_compute_s<<<dim3(16, B_, 4), 256>>>(prop_state, W_in, W_out, round);
        k_prop_mma<<<dim3(8, B_, 2), 256, MM_SMEM>>>(A);
        k_gates<<<dim3(16, B_), 256, GATES_SMEM>>>(prop_state, round);
    }
    k_readout<<<2000, 256>>>(annotation, Wo1, Wo2, out);
}